// round 12
// baseline (speedup 1.0000x reference)
#include <cuda_runtime.h>
#include <math.h>

// ---------------------------------------------------------------------------
// Problem constants (B,3,256,448 inputs)
// ---------------------------------------------------------------------------
constexpr int BB = 4;
constexpr int HH = 256, WW = 448;
constexpr int HWF = HH * WW;                      // 114688
constexpr int H2 = 128, W2 = 224, HW2 = H2 * W2;  // 28672
constexpr int H4 = 64,  W4 = 112, HW4 = H4 * W4;  // 7168

constexpr long long N0 = (long long)BB * 6   * HWF;
constexpr long long N1 = (long long)BB * 64  * HWF;
constexpr long long N2 = (long long)BB * 128 * HW2;
constexpr long long N3 = (long long)BB * 192 * HW4;
constexpr long long SEC0 = 0;
constexpr long long SEC1 = SEC0 + N0;
constexpr long long SEC2 = SEC1 + N1;
constexpr long long SEC3 = SEC2 + N2;
constexpr long long SEC4 = SEC3 + N3;

// NHWC channel counts: src (warp source) and acc (splat accumulator, +den+pad)
constexpr int CF = 36, CFA = 40;   // full res:   [f1 32][img 3][sig 1] | +den
constexpr int CHh = 64, CHA = 68;  // half res:   f2                    | +den
constexpr int CQ = 96, CQA = 100;  // quarter:    f3                    | +den

// ---------------------------------------------------------------------------
// Device scratch (no allocations allowed -> __device__ globals)
// ---------------------------------------------------------------------------
__device__ __align__(16) float g_srcF[2][(size_t)BB * HWF * CF];
__device__ __align__(16) float g_accF[2][(size_t)BB * HWF * CFA];
__device__ __align__(16) float g_srcH[2][(size_t)BB * HW2 * CHh];
__device__ __align__(16) float g_accH[2][(size_t)BB * HW2 * CHA];
__device__ __align__(16) float g_srcQ[2][(size_t)BB * HW4 * CQ];
__device__ __align__(16) float g_accQ[2][(size_t)BB * HW4 * CQA];
__device__ __align__(16) float g_bufA[2][(size_t)BB * HWF * 32];
__device__ __align__(16) float g_bufB[2][(size_t)BB * HW2 * 64];
__device__ __align__(16) float g_bufC[2][(size_t)BB * HW4 * 96];
__device__ __align__(16) float g_flow0t[BB * 2 * HWF];
__device__ __align__(16) float g_flow1t[BB * 2 * HWF];
__device__ __align__(16) float g_flowH[2][BB * 2 * HW2];
__device__ __align__(16) float g_flowQ[2][BB * 2 * HW4];
__device__ float g_meanAcc[BB];

// ---------------------------------------------------------------------------
// Packed fp32x2 helpers (sm_100 packed FMA path)
// ---------------------------------------------------------------------------
__device__ __forceinline__ unsigned long long pack2(float v) {
    unsigned long long r;
    asm("mov.b64 %0, {%1, %1};" : "=l"(r) : "r"(__float_as_uint(v)));
    return r;
}
__device__ __forceinline__ void ffma2(unsigned long long& d,
                                      unsigned long long a, unsigned long long b) {
    asm("fma.rn.f32x2 %0, %1, %2, %0;" : "+l"(d) : "l"(a), "l"(b));
}
__device__ __forceinline__ float2 unpack2(unsigned long long v) {
    float2 f;
    asm("mov.b64 {%0, %1}, %2;" : "=f"(f.x), "=f"(f.y) : "l"(v));
    return f;
}
__device__ __forceinline__ void red4(float* p, float a, float b, float c, float d) {
    asm volatile("red.global.add.v4.f32 [%0], {%1, %2, %3, %4};"
                 :: "l"(p), "f"(a), "f"(b), "f"(c), "f"(d) : "memory");
}

// ---------------------------------------------------------------------------
// Utility kernels
// ---------------------------------------------------------------------------
__global__ void zero_kernel(float4* __restrict__ p, long long n4) {
    long long i = (long long)blockIdx.x * blockDim.x + threadIdx.x;
    if (i < n4) p[i] = make_float4(0.f, 0.f, 0.f, 0.f);
}

__global__ void zero_mean_kernel(float* __restrict__ p) {
    if (threadIdx.x < BB) p[threadIdx.x] = 0.f;
}

// stage 1: 32 blocks per batch, grid-strided float4 partial sums, atomic combine
__global__ void mean_partial_kernel(const float* __restrict__ img0,
                                    const float* __restrict__ img1,
                                    float* __restrict__ acc) {
    __shared__ float red[256];
    const int b = blockIdx.x >> 5;          // 4 batches x 32 slices
    const int slice = blockIdx.x & 31;
    const float4* p0 = reinterpret_cast<const float4*>(img0 + (size_t)b * 3 * HWF);
    const float4* p1 = reinterpret_cast<const float4*>(img1 + (size_t)b * 3 * HWF);
    const int n4 = 3 * HWF / 4;             // 86016
    float s = 0.f;
    for (int i = slice * 256 + threadIdx.x; i < n4; i += 32 * 256) {
        float4 a = p0[i], c = p1[i];
        s += (a.x + a.y) + (a.z + a.w) + (c.x + c.y) + (c.z + c.w);
    }
    red[threadIdx.x] = s;
    __syncthreads();
    for (int k = 128; k > 0; k >>= 1) {
        if (threadIdx.x < k) red[threadIdx.x] += red[threadIdx.x + k];
        __syncthreads();
    }
    if (threadIdx.x == 0) atomicAdd(acc + b, red[0]);
}

// mean-subtract images + sigma copy into srcF channels [32..35] (NHWC)
__global__ void prep_kernel(const float* __restrict__ img0,
                            const float* __restrict__ img1,
                            const float* __restrict__ sig01,
                            const float* __restrict__ sig10,
                            const float* __restrict__ mn,
                            float* __restrict__ srcF0, float* __restrict__ srcF1) {
    int id = blockIdx.x * blockDim.x + threadIdx.x;
    const int n = BB * HWF;
    if (id >= 2 * n) return;
    int sel = id >= n;
    int r = sel ? id - n : id;
    int b = r / HWF;
    int p = r - b * HWF;
    float m = mn[b] * (1.f / (6.f * HWF));
    const float* im = sel ? img1 : img0;
    const float* sg = sel ? sig10 : sig01;
    float4 v;
    v.x = im[((size_t)b * 3 + 0) * HWF + p] - m;
    v.y = im[((size_t)b * 3 + 1) * HWF + p] - m;
    v.z = im[((size_t)b * 3 + 2) * HWF + p] - m;
    v.w = sg[(size_t)b * HWF + p];
    float* dst = (sel ? srcF1 : srcF0) + ((size_t)r) * CF + 32;
    *reinterpret_cast<float4*>(dst) = v;
}

// cal_inter_flow with t = 0.5 for both directions (planar NCHW flow out)
__global__ void interflow_kernel(const float* __restrict__ flow01,
                                 const float* __restrict__ sig01,
                                 const float* __restrict__ flow10,
                                 const float* __restrict__ sig10,
                                 float* __restrict__ f0t, float* __restrict__ f1t) {
    int id = blockIdx.x * blockDim.x + threadIdx.x;
    const int n = 2 * BB * HWF;
    if (id >= n) return;
    int sel = id / (BB * HWF);
    int r = id - sel * (BB * HWF);
    int b = r / HWF;
    int p = r - b * HWF;
    const float* fl = sel ? flow10 : flow01;
    const float* sg = sel ? sig10 : sig01;
    float* dst = sel ? f1t : f0t;
    float fx = fl[((size_t)b * 2) * HWF + p];
    float fy = fl[((size_t)b * 2 + 1) * HWF + p];
    float s  = sg[(size_t)b * HWF + p];
    const float t = 0.5f;
    float ftx, fty;
    if (fabsf(s) < 0.01f) {
        ftx = t * fx;
        fty = t * fy;
    } else {
        float alpha = atan2f(fy, fx);
        float beta  = asinf(s);
        float d     = sqrtf(fx * fx + fy * fy);
        float R     = d / (2.f * s);
        const float PIH = 1.57079632679489662f;
        float th0 = alpha + PIH + beta;
        float th1 = alpha + PIH - beta;
        float tht = th0 + (th1 - th0) * t;
        ftx = R * (cosf(tht) - cosf(th0));
        fty = R * (sinf(tht) - sinf(th0));
    }
    dst[((size_t)b * 2) * HWF + p]     = ftx;
    dst[((size_t)b * 2 + 1) * HWF + p] = fty;
}

// jax.image.resize(bilinear, antialias=True) exact-factor downsample + 1/f scale
__global__ void downflow_kernel(const float* __restrict__ fl, float* __restrict__ o,
                                int f, int ho, int wo) {
    const int hw = ho * wo;
    const int n = BB * 2 * hw;
    int id = blockIdx.x * blockDim.x + threadIdx.x;
    if (id >= n) return;
    int p = id % hw;
    int c = (id / hw) & 1;
    int b = id / (2 * hw);
    int oy = p / wo, ox = p % wo;
    float invf = 1.f / f;
    float sy = f * oy + (f - 1) * 0.5f;
    float sx = f * ox + (f - 1) * 0.5f;
    float wy[8], wxv[8];
    int jys[8], jxs[8];
    int ny = 0, nx = 0;
    float sumy = 0.f, sumx = 0.f;
    int jy0 = (int)floorf(sy) - f + 1;
    int jx0 = (int)floorf(sx) - f + 1;
    for (int k = 0; k < 2 * f; k++) {
        int jy = jy0 + k;
        float wv = 1.f - fabsf(jy - sy) * invf;
        if (jy >= 0 && jy < HH && wv > 0.f) { wy[ny] = wv; jys[ny] = jy; ny++; sumy += wv; }
        int jx = jx0 + k;
        wv = 1.f - fabsf(jx - sx) * invf;
        if (jx >= 0 && jx < WW && wv > 0.f) { wxv[nx] = wv; jxs[nx] = jx; nx++; sumx += wv; }
    }
    const float* ip = fl + ((size_t)b * 2 + c) * HWF;
    float acc = 0.f;
    for (int iy = 0; iy < ny; iy++) {
        const float* rp = ip + jys[iy] * WW;
        float rowacc = 0.f;
        for (int ix = 0; ix < nx; ix++) rowacc += wxv[ix] * rp[jxs[ix]];
        acc += wy[iy] * rowacc;
    }
    o[id] = acc / (sumy * sumx) * invf;
}

// ---------------------------------------------------------------------------
// conv1 specialized: raw NCHW images in (mean subtracted inline), 32ch NHWC out
// ---------------------------------------------------------------------------
template<int TW, int TH, int PX>
__global__ __launch_bounds__(TW * TH)
void conv1_kernel(const float* __restrict__ img0, const float* __restrict__ img1,
                  const float* __restrict__ mn,
                  const float* __restrict__ wgt, const float* __restrict__ bias,
                  const float* __restrict__ alpha, float* __restrict__ out) {
    constexpr int OW = PX * TW;
    constexpr int IW = OW + 2;
    constexpr int IH = TH + 2;
    constexpr int NT = TW * TH;
    constexpr int IHW = IH * IW;
    __shared__ float s_in[3 * IHW];
    __shared__ __align__(16) float s_w[3 * 9 * 32];

    const int tx = threadIdx.x, ty = threadIdx.y;
    const int tid = ty * TW + tx;
    const int b   = blockIdx.z;              // 0..7 (2 images x 4 batches)
    const int sel = b >> 2, bb = b & 3;
    const int ox0 = blockIdx.x * OW;
    const int oy0 = blockIdx.y * TH;
    const int ix0 = ox0 - 1;
    const int iy0 = oy0 - 1;
    const float m = mn[bb] * (1.f / (6.f * HWF));

    const float* im = (sel ? img1 : img0) + (size_t)bb * 3 * HWF;

    for (int idx = tid; idx < 3 * IHW; idx += NT) {
        int ci = idx / IHW;
        int pix = idx - ci * IHW;
        int iy = pix / IW, ix = pix - iy * IW;
        int gy = iy0 + iy, gx = ix0 + ix;
        float v = 0.f;
        if ((unsigned)gy < (unsigned)HH && (unsigned)gx < (unsigned)WW)
            v = im[(size_t)ci * HWF + gy * WW + gx] - m;
        s_in[idx] = v;
    }
    for (int idx = tid; idx < 3 * 9 * 32; idx += NT) {
        int co  = idx & 31;
        int rt  = idx >> 5;
        int ci  = rt / 9;
        int tap = rt - ci * 9;
        s_w[(ci * 9 + tap) * 32 + co] = wgt[((size_t)co * 3 + ci) * 9 + tap];
    }
    __syncthreads();

    unsigned long long acc[PX][16];
#pragma unroll
    for (int px = 0; px < PX; px++)
#pragma unroll
        for (int i = 0; i < 16; i++) acc[px][i] = 0ull;

#pragma unroll
    for (int ci = 0; ci < 3; ci++) {
        const float* bi = s_in + ci * IHW;
#pragma unroll
        for (int ky = 0; ky < 3; ky++) {
#pragma unroll
            for (int kx = 0; kx < 3; kx++) {
                unsigned long long vv[PX];
#pragma unroll
                for (int px = 0; px < PX; px++)
                    vv[px] = pack2(bi[(ty + ky) * IW + tx + px * TW + kx]);
                const ulonglong2* wp = reinterpret_cast<const ulonglong2*>(
                    s_w + (ci * 9 + ky * 3 + kx) * 32);
#pragma unroll
                for (int j = 0; j < 8; j++) {
                    ulonglong2 w2 = wp[j];
#pragma unroll
                    for (int px = 0; px < PX; px++) {
                        ffma2(acc[px][2 * j],     vv[px], w2.x);
                        ffma2(acc[px][2 * j + 1], vv[px], w2.y);
                    }
                }
            }
        }
    }

    const float al = __ldg(alpha);
    const int oy = oy0 + ty;
#pragma unroll
    for (int px = 0; px < PX; px++) {
        const int ox = ox0 + tx + px * TW;
        if (ox < WW && oy < HH) {
            float* op = out + ((size_t)b * HWF + (size_t)oy * WW + ox) * 32;
#pragma unroll
            for (int j = 0; j < 8; j++) {
                float2 p0 = unpack2(acc[px][2 * j]);
                float2 p1 = unpack2(acc[px][2 * j + 1]);
                float4 o4;
                float r;
                r = p0.x + __ldg(bias + 4 * j + 0); o4.x = r > 0.f ? r : al * r;
                r = p0.y + __ldg(bias + 4 * j + 1); o4.y = r > 0.f ? r : al * r;
                r = p1.x + __ldg(bias + 4 * j + 2); o4.z = r > 0.f ? r : al * r;
                r = p1.y + __ldg(bias + 4 * j + 3); o4.w = r > 0.f ? r : al * r;
                reinterpret_cast<float4*>(op)[j] = o4;
            }
        }
    }
}

// ---------------------------------------------------------------------------
// Wide-pixel conv: each thread = PXC contiguous out pixels x 8 couts.
// IW padded to multiple of 4 so per-thread input rows are 16B-aligned ->
// vin loads via LDS.128/LDS.64 instead of 10 scalar LDS. Stride 1/2.
// ---------------------------------------------------------------------------
template<int CINC, int STRIDE, int PXC, int NX, int NY, int MB>
__global__ __launch_bounds__(4 * NX * NY, MB)
void conv_wide2(const float* __restrict__ in, int CinStr, int Cin,
                const float* __restrict__ wgt, const float* __restrict__ bias,
                const float* __restrict__ alpha,
                float* __restrict__ out, int CoutStr, int Cout,
                int Hin, int Win, int Hout, int Wout) {
    constexpr int OW = NX * PXC;
    constexpr int IWR = OW * STRIDE + 2;            // needed columns
    constexpr int IW = (IWR + 3) & ~3;              // pad to 16B alignment
    constexpr int IH = NY * STRIDE + 2;
    constexpr int IHW = IH * IW;
    constexpr int NT = 4 * NX * NY;
    constexpr int VN = PXC * STRIDE + 2;
    __shared__ __align__(16) float s_in[CINC * IHW];
    __shared__ __align__(16) float s_w[CINC * 9 * 32];

    const int g  = threadIdx.x & 3;          // co-group (8 couts)
    const int xt = threadIdx.x >> 2;         // x-tile within block
    const int ty = threadIdx.y;              // row
    const int tid = ty * (4 * NX) + threadIdx.x;
    const int nCo = Cout >> 5;
    const int b      = blockIdx.z / nCo;
    const int co0blk = (blockIdx.z % nCo) << 5;
    const int co0    = co0blk + g * 8;
    const int ox0 = blockIdx.x * OW;
    const int oy0 = blockIdx.y * NY;
    const int ix0 = ox0 * STRIDE - 1, iy0 = oy0 * STRIDE - 1;
    const float* inB = in + (size_t)b * Hin * Win * CinStr;

    unsigned long long acc[PXC][4];
#pragma unroll
    for (int p = 0; p < PXC; p++)
#pragma unroll
        for (int j = 0; j < 4; j++) acc[p][j] = 0ull;

    for (int cc = 0; cc < Cin; cc += CINC) {
        __syncthreads();
        {
            constexpr int Q = CINC / 4;
            for (int idx = tid; idx < IHW * Q; idx += NT) {
                int pix = idx / Q, q = idx - (idx / Q) * Q;
                int iy = pix / IW, ix = pix - iy * IW;
                int gy = iy0 + iy, gx = ix0 + ix;
                float4 v = make_float4(0.f, 0.f, 0.f, 0.f);
                if (ix < IWR && (unsigned)gy < (unsigned)Hin && (unsigned)gx < (unsigned)Win)
                    v = *reinterpret_cast<const float4*>(
                        inB + ((size_t)gy * Win + gx) * CinStr + cc + 4 * q);
                s_in[(4 * q + 0) * IHW + pix] = v.x;
                s_in[(4 * q + 1) * IHW + pix] = v.y;
                s_in[(4 * q + 2) * IHW + pix] = v.z;
                s_in[(4 * q + 3) * IHW + pix] = v.w;
            }
        }
        for (int idx = tid; idx < CINC * 9 * 32; idx += NT) {
            int co  = idx & 31;
            int rt  = idx >> 5;
            int ci  = rt / 9;
            int tap = rt - ci * 9;
            s_w[(ci * 9 + tap) * 32 + co] =
                wgt[((size_t)(co0blk + co) * Cin + cc + ci) * 9 + tap];
        }
        __syncthreads();

        for (int ci = 0; ci < CINC; ci++) {
            const float* rp0 = s_in + ci * IHW + xt * PXC * STRIDE;
#pragma unroll
            for (int ky = 0; ky < 3; ky++) {
                const float* rp = rp0 + (ty * STRIDE + ky) * IW;   // 16B aligned
                float fin[VN];
#pragma unroll
                for (int i = 0; i < VN / 4; i++)
                    *reinterpret_cast<float4*>(fin + 4 * i) =
                        *reinterpret_cast<const float4*>(rp + 4 * i);
                if constexpr ((VN & 3) == 2)
                    *reinterpret_cast<float2*>(fin + VN - 2) =
                        *reinterpret_cast<const float2*>(rp + VN - 2);
                unsigned long long vin[VN];
#pragma unroll
                for (int i = 0; i < VN; i++) vin[i] = pack2(fin[i]);
#pragma unroll
                for (int kx = 0; kx < 3; kx++) {
                    const ulonglong2* wp = reinterpret_cast<const ulonglong2*>(
                        s_w + (ci * 9 + ky * 3 + kx) * 32) + g * 2;
                    ulonglong2 wA = wp[0];
                    ulonglong2 wB = wp[1];
#pragma unroll
                    for (int p = 0; p < PXC; p++) {
                        unsigned long long v = vin[p * STRIDE + kx];
                        ffma2(acc[p][0], v, wA.x);
                        ffma2(acc[p][1], v, wA.y);
                        ffma2(acc[p][2], v, wB.x);
                        ffma2(acc[p][3], v, wB.y);
                    }
                }
            }
        }
    }

    const float al = __ldg(alpha);
    const float4 b0 = *reinterpret_cast<const float4*>(bias + co0);
    const float4 b1 = *reinterpret_cast<const float4*>(bias + co0 + 4);
    const int oy = oy0 + ty;
    float* orow = out + ((size_t)b * Hout * Wout + (size_t)oy * Wout + ox0 + xt * PXC) * CoutStr + co0;
#pragma unroll
    for (int p = 0; p < PXC; p++) {
        float* op = orow + (size_t)p * CoutStr;
        float2 p0 = unpack2(acc[p][0]);
        float2 p1 = unpack2(acc[p][1]);
        float2 p2 = unpack2(acc[p][2]);
        float2 p3 = unpack2(acc[p][3]);
        float4 o4;
        float r;
        r = p0.x + b0.x; o4.x = r > 0.f ? r : al * r;
        r = p0.y + b0.y; o4.y = r > 0.f ? r : al * r;
        r = p1.x + b0.z; o4.z = r > 0.f ? r : al * r;
        r = p1.y + b0.w; o4.w = r > 0.f ? r : al * r;
        reinterpret_cast<float4*>(op)[0] = o4;
        r = p2.x + b1.x; o4.x = r > 0.f ? r : al * r;
        r = p2.y + b1.y; o4.y = r > 0.f ? r : al * r;
        r = p3.x + b1.z; o4.z = r > 0.f ? r : al * r;
        r = p3.y + b1.w; o4.w = r > 0.f ? r : al * r;
        reinterpret_cast<float4*>(op)[1] = o4;
    }
}

// ---------------------------------------------------------------------------
// Forward-warp scatter: NHWC src, NHWC acc (den at channel C), v4 reductions.
// ---------------------------------------------------------------------------
template<int C4, int CA>
__global__ void scatter_kernel(const float* __restrict__ src,
                               const float* __restrict__ flow,
                               float* __restrict__ acc, int Hs, int Ws) {
    constexpr int C = 4 * C4;
    const int HWs = Hs * Ws;
    int id = blockIdx.x * blockDim.x + threadIdx.x;
    if (id >= BB * HWs) return;
    int b = id / HWs;
    int p = id - b * HWs;
    int y = p / Ws;
    int x = p - y * Ws;
    const float* fb = flow + (size_t)b * 2 * HWs;
    float fx = fb[p], fy = fb[HWs + p];
    float txf = x + fx, tyf = y + fy;
    float x0f = floorf(txf), y0f = floorf(tyf);
    float dx = txf - x0f, dy = tyf - y0f;
    int x0 = (int)x0f, y0 = (int)y0f;
    float w[4] = { (1.f - dx) * (1.f - dy), dx * (1.f - dy),
                   (1.f - dx) * dy,         dx * dy };
    int xs[4] = { x0, x0 + 1, x0, x0 + 1 };
    int ys[4] = { y0, y0, y0 + 1, y0 + 1 };
    int idxs[4];
    bool ok[4];
#pragma unroll
    for (int k = 0; k < 4; k++) {
        ok[k] = xs[k] >= 0 && xs[k] < Ws && ys[k] >= 0 && ys[k] < Hs && w[k] > 0.f;
        idxs[k] = ys[k] * Ws + xs[k];
    }
    float* accB = acc + (size_t)b * HWs * CA;
    const float4* sp = reinterpret_cast<const float4*>(src + (size_t)id * C);
#pragma unroll
    for (int c4 = 0; c4 < C4; c4++) {
        float4 v = sp[c4];
#pragma unroll
        for (int k = 0; k < 4; k++) {
            if (ok[k])
                red4(accB + (size_t)idxs[k] * CA + 4 * c4,
                     v.x * w[k], v.y * w[k], v.z * w[k], v.w * w[k]);
        }
    }
#pragma unroll
    for (int k = 0; k < 4; k++)
        if (ok[k]) atomicAdd(accB + (size_t)idxs[k] * CA + C, w[k]);
}

// ---------------------------------------------------------------------------
// Finalize: NHWC acc -> divide by den -> NCHW output sections
// ---------------------------------------------------------------------------
template<int C, int CA>
__global__ void finalize_simple(const float* __restrict__ acc,
                                float* __restrict__ outsec,
                                int Ctot, int coff, int HWs) {
    __shared__ float s[64 * (CA + 1)];
    __shared__ float inv[64];
    const int base = blockIdx.x * 64;
    const int tid = threadIdx.x;
    constexpr int Q = CA / 4;
    for (int idx = tid; idx < 64 * Q; idx += 256) {
        int p = idx / Q, q = idx - (idx / Q) * Q;
        float4 v = *reinterpret_cast<const float4*>(acc + ((size_t)(base + p)) * CA + 4 * q);
        s[p * (CA + 1) + 4 * q + 0] = v.x;
        s[p * (CA + 1) + 4 * q + 1] = v.y;
        s[p * (CA + 1) + 4 * q + 2] = v.z;
        s[p * (CA + 1) + 4 * q + 3] = v.w;
    }
    __syncthreads();
    if (tid < 64) inv[tid] = 1.f / fmaxf(s[tid * (CA + 1) + C], 1e-7f);
    __syncthreads();
    const int b = base / HWs;
    const int p0 = base - b * HWs;
    for (int id = tid; id < C * 64; id += 256) {
        int c = id >> 6, i = id & 63;
        outsec[((size_t)(b * Ctot + coff + c)) * HWs + p0 + i] = s[i * (CA + 1) + c] * inv[i];
    }
}

// full-res: channels 0-31 -> SEC1(feat), 32-34 -> SEC0(img), 35 -> SEC4(sig)
__global__ void finalize_full(const float* __restrict__ acc,
                              float* __restrict__ out, int sel) {
    __shared__ float s[64 * 41];
    __shared__ float inv[64];
    const int base = blockIdx.x * 64;
    const int tid = threadIdx.x;
    for (int idx = tid; idx < 64 * 10; idx += 256) {
        int p = idx / 10, q = idx - (idx / 10) * 10;
        float4 v = *reinterpret_cast<const float4*>(acc + ((size_t)(base + p)) * CFA + 4 * q);
        s[p * 41 + 4 * q + 0] = v.x;
        s[p * 41 + 4 * q + 1] = v.y;
        s[p * 41 + 4 * q + 2] = v.z;
        s[p * 41 + 4 * q + 3] = v.w;
    }
    __syncthreads();
    if (tid < 64) inv[tid] = 1.f / fmaxf(s[tid * 41 + 36], 1e-7f);
    __syncthreads();
    const int b = base / HWF;
    const int p0 = base - b * HWF;
    for (int id = tid; id < 36 * 64; id += 256) {
        int c = id >> 6, i = id & 63;
        float val = s[i * 41 + c] * inv[i];
        size_t dst;
        if (c < 32)       dst = SEC1 + ((size_t)(b * 64 + 32 * sel + c)) * HWF + p0 + i;
        else if (c < 35)  dst = SEC0 + ((size_t)(b * 6 + 3 * sel + (c - 32))) * HWF + p0 + i;
        else              dst = SEC4 + ((size_t)(b * 2 + sel)) * HWF + p0 + i;
        out[dst] = val;
    }
}

// ---------------------------------------------------------------------------
// Host launcher with multi-stream graph (forked from capturing default stream)
// ---------------------------------------------------------------------------
static inline int div_up(long long a, int b) { return (int)((a + b - 1) / b); }

extern "C" void kernel_launch(void* const* d_in, const int* in_sizes, int n_in,
                              void* d_out, int out_size) {
    const float* img0    = (const float*)d_in[0];
    const float* img1    = (const float*)d_in[1];
    const float* flow01  = (const float*)d_in[2];
    const float* sigma01 = (const float*)d_in[3];
    const float* flow10  = (const float*)d_in[4];
    const float* sigma10 = (const float*)d_in[5];
    const float *w[6], *bi[6], *al[6];
    for (int i = 0; i < 6; i++) {
        w[i]  = (const float*)d_in[6 + 3 * i];
        bi[i] = (const float*)d_in[7 + 3 * i];
        al[i] = (const float*)d_in[8 + 3 * i];
    }
    float* out = (float*)d_out;

    float *p_srcF, *p_accF, *p_srcH, *p_accH, *p_srcQ, *p_accQ;
    float *p_bufA, *p_bufB, *p_bufC, *p_f0t, *p_f1t, *p_fH, *p_fQ, *p_mean;
    cudaGetSymbolAddress((void**)&p_srcF, g_srcF);
    cudaGetSymbolAddress((void**)&p_accF, g_accF);
    cudaGetSymbolAddress((void**)&p_srcH, g_srcH);
    cudaGetSymbolAddress((void**)&p_accH, g_accH);
    cudaGetSymbolAddress((void**)&p_srcQ, g_srcQ);
    cudaGetSymbolAddress((void**)&p_accQ, g_accQ);
    cudaGetSymbolAddress((void**)&p_bufA, g_bufA);
    cudaGetSymbolAddress((void**)&p_bufB, g_bufB);
    cudaGetSymbolAddress((void**)&p_bufC, g_bufC);
    cudaGetSymbolAddress((void**)&p_f0t,  g_flow0t);
    cudaGetSymbolAddress((void**)&p_f1t,  g_flow1t);
    cudaGetSymbolAddress((void**)&p_fH,   g_flowH);
    cudaGetSymbolAddress((void**)&p_fQ,   g_flowQ);
    cudaGetSymbolAddress((void**)&p_mean, g_meanAcc);

    const size_t szSF = (size_t)BB * HWF * CF;
    const size_t szAF = (size_t)BB * HWF * CFA;
    const size_t szSH = (size_t)BB * HW2 * CHh;
    const size_t szAH = (size_t)BB * HW2 * CHA;
    const size_t szSQ = (size_t)BB * HW4 * CQ;
    const size_t szAQ = (size_t)BB * HW4 * CQA;

    // Lazily-created side streams + events (first call is the uncaptured
    // correctness run, so creation happens outside graph capture).
    static cudaStream_t sA = nullptr, sB = nullptr, sC = nullptr;
    static cudaEvent_t evRoot, evMean, evC2, evC4, evS1, evSB, evSC;
    if (!sA) {
        cudaStreamCreateWithFlags(&sA, cudaStreamNonBlocking);
        cudaStreamCreateWithFlags(&sB, cudaStreamNonBlocking);
        cudaStreamCreateWithFlags(&sC, cudaStreamNonBlocking);
        cudaEventCreateWithFlags(&evRoot, cudaEventDisableTiming);
        cudaEventCreateWithFlags(&evMean, cudaEventDisableTiming);
        cudaEventCreateWithFlags(&evC2,   cudaEventDisableTiming);
        cudaEventCreateWithFlags(&evC4,   cudaEventDisableTiming);
        cudaEventCreateWithFlags(&evS1,   cudaEventDisableTiming);
        cudaEventCreateWithFlags(&evSB,   cudaEventDisableTiming);
        cudaEventCreateWithFlags(&evSC,   cudaEventDisableTiming);
    }

    // ---- main stream M (default): mean chain + conv chain ----
    cudaEventRecord(evRoot, 0);

    zero_mean_kernel<<<1, 32>>>(p_mean);
    mean_partial_kernel<<<BB * 32, 256>>>(img0, img1, p_mean);
    cudaEventRecord(evMean, 0);

    conv1_kernel<16, 4, 4><<<dim3(7, 64, 8), dim3(16, 4)>>>(
        img0, img1, p_mean, w[0], bi[0], al[0], p_bufA);
    // launch index 3 (ncu-profiled): conv2, vectorized-input wide kernel
    conv_wide2<8, 1, 8, 4, 8, 4><<<dim3(14, 32, 8), dim3(16, 8)>>>(
        p_bufA, 32, 32, w[1], bi[1], al[1], p_srcF, CF, 32, HH, WW, HH, WW);
    cudaEventRecord(evC2, 0);

    // conv3: stride2, reshaped to NY=4 (64 thr) to fit padded smem
    conv_wide2<8, 2, 8, 4, 4, 4><<<dim3(7, 32, 16), dim3(16, 4)>>>(
        p_srcF, CF, 32, w[2], bi[2], al[2], p_bufB, 64, 64, HH, WW, H2, W2);
    conv_wide2<8, 1, 8, 4, 8, 4><<<dim3(7, 16, 16), dim3(16, 8)>>>(
        p_bufB, 64, 64, w[3], bi[3], al[3], p_srcH, CHh, 64, H2, W2, H2, W2);
    cudaEventRecord(evC4, 0);

    conv_wide2<8, 2, 8, 2, 8, 2><<<dim3(7, 8, 24), dim3(8, 8)>>>(
        p_srcH, CHh, 64, w[4], bi[4], al[4], p_bufC, 96, 96, H2, W2, H4, W4);
    conv_wide2<8, 1, 8, 2, 8, 2><<<dim3(7, 8, 24), dim3(8, 8)>>>(
        p_bufC, 96, 96, w[5], bi[5], al[5], p_srcQ, CQ, 96, H4, W4, H4, W4);

    // ---- stream A: flows + acc zeros + prep (overlaps conv chain) ----
    cudaStreamWaitEvent(sA, evRoot, 0);
    interflow_kernel<<<div_up(2LL * BB * HWF, 256), 256, 0, sA>>>(
        flow01, sigma01, flow10, sigma10, p_f0t, p_f1t);
    downflow_kernel<<<div_up((long long)BB * 2 * HW2, 256), 256, 0, sA>>>(p_f0t, p_fH, 2, H2, W2);
    downflow_kernel<<<div_up((long long)BB * 2 * HW2, 256), 256, 0, sA>>>(p_f1t, p_fH + (size_t)BB * 2 * HW2, 2, H2, W2);
    downflow_kernel<<<div_up((long long)BB * 2 * HW4, 256), 256, 0, sA>>>(p_f0t, p_fQ, 4, H4, W4);
    downflow_kernel<<<div_up((long long)BB * 2 * HW4, 256), 256, 0, sA>>>(p_f1t, p_fQ + (size_t)BB * 2 * HW4, 4, H4, W4);
    zero_kernel<<<div_up(2LL * szAF / 4, 256), 256, 0, sA>>>((float4*)p_accF, 2LL * szAF / 4);
    zero_kernel<<<div_up(2LL * szAH / 4, 256), 256, 0, sA>>>((float4*)p_accH, 2LL * szAH / 4);
    zero_kernel<<<div_up(2LL * szAQ / 4, 256), 256, 0, sA>>>((float4*)p_accQ, 2LL * szAQ / 4);
    cudaStreamWaitEvent(sA, evMean, 0);
    prep_kernel<<<div_up(2LL * BB * HWF, 256), 256, 0, sA>>>(
        img0, img1, sigma01, sigma10, p_mean, p_srcF, p_srcF + szSF);
    cudaEventRecord(evS1, sA);

    // ---- stream B: full-res scatter + finalize (overlaps conv3..6) ----
    cudaStreamWaitEvent(sB, evC2, 0);
    cudaStreamWaitEvent(sB, evS1, 0);
    for (int sel = 0; sel < 2; sel++) {
        const float* flF = sel ? p_f1t : p_f0t;
        scatter_kernel<9, CFA><<<div_up((long long)BB * HWF, 256), 256, 0, sB>>>(
            p_srcF + (size_t)sel * szSF, flF, p_accF + (size_t)sel * szAF, HH, WW);
    }
    for (int sel = 0; sel < 2; sel++)
        finalize_full<<<BB * HWF / 64, 256, 0, sB>>>(p_accF + (size_t)sel * szAF, out, sel);
    cudaEventRecord(evSB, sB);

    // ---- stream C: half-res scatter + finalize (overlaps conv5/6) ----
    cudaStreamWaitEvent(sC, evC4, 0);
    cudaStreamWaitEvent(sC, evS1, 0);
    for (int sel = 0; sel < 2; sel++) {
        const float* flH = p_fH + (size_t)sel * BB * 2 * HW2;
        scatter_kernel<16, CHA><<<div_up((long long)BB * HW2, 256), 256, 0, sC>>>(
            p_srcH + (size_t)sel * szSH, flH, p_accH + (size_t)sel * szAH, H2, W2);
    }
    for (int sel = 0; sel < 2; sel++)
        finalize_simple<CHh, CHA><<<BB * HW2 / 64, 256, 0, sC>>>(
            p_accH + (size_t)sel * szAH, out + SEC2, 128, 64 * sel, HW2);
    cudaEventRecord(evSC, sC);

    // ---- main stream tail: quarter-res after conv6 ----
    cudaStreamWaitEvent(0, evS1, 0);
    for (int sel = 0; sel < 2; sel++) {
        const float* flQ = p_fQ + (size_t)sel * BB * 2 * HW4;
        scatter_kernel<24, CQA><<<div_up((long long)BB * HW4, 256), 256>>>(
            p_srcQ + (size_t)sel * szSQ, flQ, p_accQ + (size_t)sel * szAQ, H4, W4);
    }
    for (int sel = 0; sel < 2; sel++)
        finalize_simple<CQ, CQA><<<BB * HW4 / 64, 256>>>(
            p_accQ + (size_t)sel * szAQ, out + SEC3, 192, 96 * sel, HW4);

    // ---- join side streams back into the default stream ----
    cudaStreamWaitEvent(0, evSB, 0);
    cudaStreamWaitEvent(0, evSC, 0);
}

// round 13
// speedup vs baseline: 1.0324x; 1.0324x over previous
#include <cuda_runtime.h>
#include <math.h>

// ---------------------------------------------------------------------------
// Problem constants (B,3,256,448 inputs)
// ---------------------------------------------------------------------------
constexpr int BB = 4;
constexpr int HH = 256, WW = 448;
constexpr int HWF = HH * WW;                      // 114688
constexpr int H2 = 128, W2 = 224, HW2 = H2 * W2;  // 28672
constexpr int H4 = 64,  W4 = 112, HW4 = H4 * W4;  // 7168

constexpr long long N0 = (long long)BB * 6   * HWF;
constexpr long long N1 = (long long)BB * 64  * HWF;
constexpr long long N2 = (long long)BB * 128 * HW2;
constexpr long long N3 = (long long)BB * 192 * HW4;
constexpr long long SEC0 = 0;
constexpr long long SEC1 = SEC0 + N0;
constexpr long long SEC2 = SEC1 + N1;
constexpr long long SEC3 = SEC2 + N2;
constexpr long long SEC4 = SEC3 + N3;

// NHWC channel counts: src (warp source) and acc (splat accumulator, +den+pad)
constexpr int CF = 36, CFA = 40;   // full res:   [f1 32][img 3][sig 1] | +den
constexpr int CHh = 64, CHA = 68;  // half res:   f2                    | +den
constexpr int CQ = 96, CQA = 100;  // quarter:    f3                    | +den

// ---------------------------------------------------------------------------
// Device scratch (no allocations allowed -> __device__ globals)
// ---------------------------------------------------------------------------
__device__ __align__(16) float g_srcF[2][(size_t)BB * HWF * CF];
__device__ __align__(16) float g_accF[2][(size_t)BB * HWF * CFA];
__device__ __align__(16) float g_srcH[2][(size_t)BB * HW2 * CHh];
__device__ __align__(16) float g_accH[2][(size_t)BB * HW2 * CHA];
__device__ __align__(16) float g_srcQ[2][(size_t)BB * HW4 * CQ];
__device__ __align__(16) float g_accQ[2][(size_t)BB * HW4 * CQA];
__device__ __align__(16) float g_bufA[2][(size_t)BB * HWF * 32];
__device__ __align__(16) float g_bufB[2][(size_t)BB * HW2 * 64];
__device__ __align__(16) float g_bufC[2][(size_t)BB * HW4 * 96];
__device__ __align__(16) float g_flow0t[BB * 2 * HWF];
__device__ __align__(16) float g_flow1t[BB * 2 * HWF];
__device__ __align__(16) float g_flowH[2][BB * 2 * HW2];
__device__ __align__(16) float g_flowQ[2][BB * 2 * HW4];
__device__ float g_meanAcc[BB];

// ---------------------------------------------------------------------------
// Packed fp32x2 helpers (sm_100 packed FMA path)
// ---------------------------------------------------------------------------
__device__ __forceinline__ unsigned long long pack2(float v) {
    unsigned long long r;
    asm("mov.b64 %0, {%1, %1};" : "=l"(r) : "r"(__float_as_uint(v)));
    return r;
}
__device__ __forceinline__ void ffma2(unsigned long long& d,
                                      unsigned long long a, unsigned long long b) {
    asm("fma.rn.f32x2 %0, %1, %2, %0;" : "+l"(d) : "l"(a), "l"(b));
}
__device__ __forceinline__ float2 unpack2(unsigned long long v) {
    float2 f;
    asm("mov.b64 {%0, %1}, %2;" : "=f"(f.x), "=f"(f.y) : "l"(v));
    return f;
}
__device__ __forceinline__ void red4(float* p, float a, float b, float c, float d) {
    asm volatile("red.global.add.v4.f32 [%0], {%1, %2, %3, %4};"
                 :: "l"(p), "f"(a), "f"(b), "f"(c), "f"(d) : "memory");
}

// ---------------------------------------------------------------------------
// Utility kernels
// ---------------------------------------------------------------------------
__global__ void zero_kernel(float4* __restrict__ p, long long n4) {
    long long i = (long long)blockIdx.x * blockDim.x + threadIdx.x;
    if (i < n4) p[i] = make_float4(0.f, 0.f, 0.f, 0.f);
}

__global__ void zero_mean_kernel(float* __restrict__ p) {
    if (threadIdx.x < BB) p[threadIdx.x] = 0.f;
}

// stage 1: 32 blocks per batch, grid-strided float4 partial sums, atomic combine
__global__ void mean_partial_kernel(const float* __restrict__ img0,
                                    const float* __restrict__ img1,
                                    float* __restrict__ acc) {
    __shared__ float red[256];
    const int b = blockIdx.x >> 5;          // 4 batches x 32 slices
    const int slice = blockIdx.x & 31;
    const float4* p0 = reinterpret_cast<const float4*>(img0 + (size_t)b * 3 * HWF);
    const float4* p1 = reinterpret_cast<const float4*>(img1 + (size_t)b * 3 * HWF);
    const int n4 = 3 * HWF / 4;             // 86016
    float s = 0.f;
    for (int i = slice * 256 + threadIdx.x; i < n4; i += 32 * 256) {
        float4 a = p0[i], c = p1[i];
        s += (a.x + a.y) + (a.z + a.w) + (c.x + c.y) + (c.z + c.w);
    }
    red[threadIdx.x] = s;
    __syncthreads();
    for (int k = 128; k > 0; k >>= 1) {
        if (threadIdx.x < k) red[threadIdx.x] += red[threadIdx.x + k];
        __syncthreads();
    }
    if (threadIdx.x == 0) atomicAdd(acc + b, red[0]);
}

// mean-subtract images + sigma copy into srcF channels [32..35] (NHWC)
__global__ void prep_kernel(const float* __restrict__ img0,
                            const float* __restrict__ img1,
                            const float* __restrict__ sig01,
                            const float* __restrict__ sig10,
                            const float* __restrict__ mn,
                            float* __restrict__ srcF0, float* __restrict__ srcF1) {
    int id = blockIdx.x * blockDim.x + threadIdx.x;
    const int n = BB * HWF;
    if (id >= 2 * n) return;
    int sel = id >= n;
    int r = sel ? id - n : id;
    int b = r / HWF;
    int p = r - b * HWF;
    float m = mn[b] * (1.f / (6.f * HWF));
    const float* im = sel ? img1 : img0;
    const float* sg = sel ? sig10 : sig01;
    float4 v;
    v.x = im[((size_t)b * 3 + 0) * HWF + p] - m;
    v.y = im[((size_t)b * 3 + 1) * HWF + p] - m;
    v.z = im[((size_t)b * 3 + 2) * HWF + p] - m;
    v.w = sg[(size_t)b * HWF + p];
    float* dst = (sel ? srcF1 : srcF0) + ((size_t)r) * CF + 32;
    *reinterpret_cast<float4*>(dst) = v;
}

// cal_inter_flow with t = 0.5 for both directions (planar NCHW flow out)
__global__ void interflow_kernel(const float* __restrict__ flow01,
                                 const float* __restrict__ sig01,
                                 const float* __restrict__ flow10,
                                 const float* __restrict__ sig10,
                                 float* __restrict__ f0t, float* __restrict__ f1t) {
    int id = blockIdx.x * blockDim.x + threadIdx.x;
    const int n = 2 * BB * HWF;
    if (id >= n) return;
    int sel = id / (BB * HWF);
    int r = id - sel * (BB * HWF);
    int b = r / HWF;
    int p = r - b * HWF;
    const float* fl = sel ? flow10 : flow01;
    const float* sg = sel ? sig10 : sig01;
    float* dst = sel ? f1t : f0t;
    float fx = fl[((size_t)b * 2) * HWF + p];
    float fy = fl[((size_t)b * 2 + 1) * HWF + p];
    float s  = sg[(size_t)b * HWF + p];
    const float t = 0.5f;
    float ftx, fty;
    if (fabsf(s) < 0.01f) {
        ftx = t * fx;
        fty = t * fy;
    } else {
        float alpha = atan2f(fy, fx);
        float beta  = asinf(s);
        float d     = sqrtf(fx * fx + fy * fy);
        float R     = d / (2.f * s);
        const float PIH = 1.57079632679489662f;
        float th0 = alpha + PIH + beta;
        float th1 = alpha + PIH - beta;
        float tht = th0 + (th1 - th0) * t;
        ftx = R * (cosf(tht) - cosf(th0));
        fty = R * (sinf(tht) - sinf(th0));
    }
    dst[((size_t)b * 2) * HWF + p]     = ftx;
    dst[((size_t)b * 2 + 1) * HWF + p] = fty;
}

// jax.image.resize(bilinear, antialias=True) exact-factor downsample + 1/f scale
__global__ void downflow_kernel(const float* __restrict__ fl, float* __restrict__ o,
                                int f, int ho, int wo) {
    const int hw = ho * wo;
    const int n = BB * 2 * hw;
    int id = blockIdx.x * blockDim.x + threadIdx.x;
    if (id >= n) return;
    int p = id % hw;
    int c = (id / hw) & 1;
    int b = id / (2 * hw);
    int oy = p / wo, ox = p % wo;
    float invf = 1.f / f;
    float sy = f * oy + (f - 1) * 0.5f;
    float sx = f * ox + (f - 1) * 0.5f;
    float wy[8], wxv[8];
    int jys[8], jxs[8];
    int ny = 0, nx = 0;
    float sumy = 0.f, sumx = 0.f;
    int jy0 = (int)floorf(sy) - f + 1;
    int jx0 = (int)floorf(sx) - f + 1;
    for (int k = 0; k < 2 * f; k++) {
        int jy = jy0 + k;
        float wv = 1.f - fabsf(jy - sy) * invf;
        if (jy >= 0 && jy < HH && wv > 0.f) { wy[ny] = wv; jys[ny] = jy; ny++; sumy += wv; }
        int jx = jx0 + k;
        wv = 1.f - fabsf(jx - sx) * invf;
        if (jx >= 0 && jx < WW && wv > 0.f) { wxv[nx] = wv; jxs[nx] = jx; nx++; sumx += wv; }
    }
    const float* ip = fl + ((size_t)b * 2 + c) * HWF;
    float acc = 0.f;
    for (int iy = 0; iy < ny; iy++) {
        const float* rp = ip + jys[iy] * WW;
        float rowacc = 0.f;
        for (int ix = 0; ix < nx; ix++) rowacc += wxv[ix] * rp[jxs[ix]];
        acc += wy[iy] * rowacc;
    }
    o[id] = acc / (sumy * sumx) * invf;
}

// ---------------------------------------------------------------------------
// conv1 specialized: raw NCHW images in (mean subtracted inline), 32ch NHWC out
// ---------------------------------------------------------------------------
template<int TW, int TH, int PX>
__global__ __launch_bounds__(TW * TH)
void conv1_kernel(const float* __restrict__ img0, const float* __restrict__ img1,
                  const float* __restrict__ mn,
                  const float* __restrict__ wgt, const float* __restrict__ bias,
                  const float* __restrict__ alpha, float* __restrict__ out) {
    constexpr int OW = PX * TW;
    constexpr int IW = OW + 2;
    constexpr int IH = TH + 2;
    constexpr int NT = TW * TH;
    constexpr int IHW = IH * IW;
    __shared__ float s_in[3 * IHW];
    __shared__ __align__(16) float s_w[3 * 9 * 32];

    const int tx = threadIdx.x, ty = threadIdx.y;
    const int tid = ty * TW + tx;
    const int b   = blockIdx.z;              // 0..7 (2 images x 4 batches)
    const int sel = b >> 2, bb = b & 3;
    const int ox0 = blockIdx.x * OW;
    const int oy0 = blockIdx.y * TH;
    const int ix0 = ox0 - 1;
    const int iy0 = oy0 - 1;
    const float m = mn[bb] * (1.f / (6.f * HWF));

    const float* im = (sel ? img1 : img0) + (size_t)bb * 3 * HWF;

    for (int idx = tid; idx < 3 * IHW; idx += NT) {
        int ci = idx / IHW;
        int pix = idx - ci * IHW;
        int iy = pix / IW, ix = pix - iy * IW;
        int gy = iy0 + iy, gx = ix0 + ix;
        float v = 0.f;
        if ((unsigned)gy < (unsigned)HH && (unsigned)gx < (unsigned)WW)
            v = im[(size_t)ci * HWF + gy * WW + gx] - m;
        s_in[idx] = v;
    }
    for (int idx = tid; idx < 3 * 9 * 32; idx += NT) {
        int co  = idx & 31;
        int rt  = idx >> 5;
        int ci  = rt / 9;
        int tap = rt - ci * 9;
        s_w[(ci * 9 + tap) * 32 + co] = wgt[((size_t)co * 3 + ci) * 9 + tap];
    }
    __syncthreads();

    unsigned long long acc[PX][16];
#pragma unroll
    for (int px = 0; px < PX; px++)
#pragma unroll
        for (int i = 0; i < 16; i++) acc[px][i] = 0ull;

#pragma unroll
    for (int ci = 0; ci < 3; ci++) {
        const float* bi = s_in + ci * IHW;
#pragma unroll
        for (int ky = 0; ky < 3; ky++) {
#pragma unroll
            for (int kx = 0; kx < 3; kx++) {
                unsigned long long vv[PX];
#pragma unroll
                for (int px = 0; px < PX; px++)
                    vv[px] = pack2(bi[(ty + ky) * IW + tx + px * TW + kx]);
                const ulonglong2* wp = reinterpret_cast<const ulonglong2*>(
                    s_w + (ci * 9 + ky * 3 + kx) * 32);
#pragma unroll
                for (int j = 0; j < 8; j++) {
                    ulonglong2 w2 = wp[j];
#pragma unroll
                    for (int px = 0; px < PX; px++) {
                        ffma2(acc[px][2 * j],     vv[px], w2.x);
                        ffma2(acc[px][2 * j + 1], vv[px], w2.y);
                    }
                }
            }
        }
    }

    const float al = __ldg(alpha);
    const int oy = oy0 + ty;
#pragma unroll
    for (int px = 0; px < PX; px++) {
        const int ox = ox0 + tx + px * TW;
        if (ox < WW && oy < HH) {
            float* op = out + ((size_t)b * HWF + (size_t)oy * WW + ox) * 32;
#pragma unroll
            for (int j = 0; j < 8; j++) {
                float2 p0 = unpack2(acc[px][2 * j]);
                float2 p1 = unpack2(acc[px][2 * j + 1]);
                float4 o4;
                float r;
                r = p0.x + __ldg(bias + 4 * j + 0); o4.x = r > 0.f ? r : al * r;
                r = p0.y + __ldg(bias + 4 * j + 1); o4.y = r > 0.f ? r : al * r;
                r = p1.x + __ldg(bias + 4 * j + 2); o4.z = r > 0.f ? r : al * r;
                r = p1.y + __ldg(bias + 4 * j + 3); o4.w = r > 0.f ? r : al * r;
                reinterpret_cast<float4*>(op)[j] = o4;
            }
        }
    }
}

// ---------------------------------------------------------------------------
// Wide-pixel conv: each thread = PXC contiguous out pixels x 8 couts.
// PAD=1: IW padded to multiple of 4, vin via LDS.128 (stride-1 layers).
// PAD=0: unpadded, scalar vin loads (stride-2 layers, smem-constrained).
// ---------------------------------------------------------------------------
template<int CINC, int STRIDE, int PXC, int NX, int NY, int MB, int PAD>
__global__ __launch_bounds__(4 * NX * NY, MB)
void conv_wide2(const float* __restrict__ in, int CinStr, int Cin,
                const float* __restrict__ wgt, const float* __restrict__ bias,
                const float* __restrict__ alpha,
                float* __restrict__ out, int CoutStr, int Cout,
                int Hin, int Win, int Hout, int Wout) {
    constexpr int OW = NX * PXC;
    constexpr int IWR = OW * STRIDE + 2;            // needed columns
    constexpr int IW = PAD ? ((IWR + 3) & ~3) : IWR;
    constexpr int IH = NY * STRIDE + 2;
    constexpr int IHW = IH * IW;
    constexpr int NT = 4 * NX * NY;
    constexpr int VN = PXC * STRIDE + 2;
    __shared__ __align__(16) float s_in[CINC * IHW];
    __shared__ __align__(16) float s_w[CINC * 9 * 32];

    const int g  = threadIdx.x & 3;          // co-group (8 couts)
    const int xt = threadIdx.x >> 2;         // x-tile within block
    const int ty = threadIdx.y;              // row
    const int tid = ty * (4 * NX) + threadIdx.x;
    const int nCo = Cout >> 5;
    const int b      = blockIdx.z / nCo;
    const int co0blk = (blockIdx.z % nCo) << 5;
    const int co0    = co0blk + g * 8;
    const int ox0 = blockIdx.x * OW;
    const int oy0 = blockIdx.y * NY;
    const int ix0 = ox0 * STRIDE - 1, iy0 = oy0 * STRIDE - 1;
    const float* inB = in + (size_t)b * Hin * Win * CinStr;

    unsigned long long acc[PXC][4];
#pragma unroll
    for (int p = 0; p < PXC; p++)
#pragma unroll
        for (int j = 0; j < 4; j++) acc[p][j] = 0ull;

    for (int cc = 0; cc < Cin; cc += CINC) {
        __syncthreads();
        {
            constexpr int Q = CINC / 4;
            for (int idx = tid; idx < IHW * Q; idx += NT) {
                int pix = idx / Q, q = idx - (idx / Q) * Q;
                int iy = pix / IW, ix = pix - iy * IW;
                int gy = iy0 + iy, gx = ix0 + ix;
                float4 v = make_float4(0.f, 0.f, 0.f, 0.f);
                bool okx = PAD ? (ix < IWR) : true;
                if (okx && (unsigned)gy < (unsigned)Hin && (unsigned)gx < (unsigned)Win)
                    v = *reinterpret_cast<const float4*>(
                        inB + ((size_t)gy * Win + gx) * CinStr + cc + 4 * q);
                s_in[(4 * q + 0) * IHW + pix] = v.x;
                s_in[(4 * q + 1) * IHW + pix] = v.y;
                s_in[(4 * q + 2) * IHW + pix] = v.z;
                s_in[(4 * q + 3) * IHW + pix] = v.w;
            }
        }
        for (int idx = tid; idx < CINC * 9 * 32; idx += NT) {
            int co  = idx & 31;
            int rt  = idx >> 5;
            int ci  = rt / 9;
            int tap = rt - ci * 9;
            s_w[(ci * 9 + tap) * 32 + co] =
                wgt[((size_t)(co0blk + co) * Cin + cc + ci) * 9 + tap];
        }
        __syncthreads();

        for (int ci = 0; ci < CINC; ci++) {
            const float* rp0 = s_in + ci * IHW + xt * PXC * STRIDE;
#pragma unroll
            for (int ky = 0; ky < 3; ky++) {
                const float* rp = rp0 + (ty * STRIDE + ky) * IW;
                unsigned long long vin[VN];
                if constexpr (PAD) {
                    float fin[VN];
#pragma unroll
                    for (int i = 0; i < VN / 4; i++)
                        *reinterpret_cast<float4*>(fin + 4 * i) =
                            *reinterpret_cast<const float4*>(rp + 4 * i);
                    if constexpr ((VN & 3) == 2)
                        *reinterpret_cast<float2*>(fin + VN - 2) =
                            *reinterpret_cast<const float2*>(rp + VN - 2);
#pragma unroll
                    for (int i = 0; i < VN; i++) vin[i] = pack2(fin[i]);
                } else {
#pragma unroll
                    for (int i = 0; i < VN; i++) vin[i] = pack2(rp[i]);
                }
#pragma unroll
                for (int kx = 0; kx < 3; kx++) {
                    const ulonglong2* wp = reinterpret_cast<const ulonglong2*>(
                        s_w + (ci * 9 + ky * 3 + kx) * 32) + g * 2;
                    ulonglong2 wA = wp[0];
                    ulonglong2 wB = wp[1];
#pragma unroll
                    for (int p = 0; p < PXC; p++) {
                        unsigned long long v = vin[p * STRIDE + kx];
                        ffma2(acc[p][0], v, wA.x);
                        ffma2(acc[p][1], v, wA.y);
                        ffma2(acc[p][2], v, wB.x);
                        ffma2(acc[p][3], v, wB.y);
                    }
                }
            }
        }
    }

    const float al = __ldg(alpha);
    const float4 b0 = *reinterpret_cast<const float4*>(bias + co0);
    const float4 b1 = *reinterpret_cast<const float4*>(bias + co0 + 4);
    const int oy = oy0 + ty;
    float* orow = out + ((size_t)b * Hout * Wout + (size_t)oy * Wout + ox0 + xt * PXC) * CoutStr + co0;
#pragma unroll
    for (int p = 0; p < PXC; p++) {
        float* op = orow + (size_t)p * CoutStr;
        float2 p0 = unpack2(acc[p][0]);
        float2 p1 = unpack2(acc[p][1]);
        float2 p2 = unpack2(acc[p][2]);
        float2 p3 = unpack2(acc[p][3]);
        float4 o4;
        float r;
        r = p0.x + b0.x; o4.x = r > 0.f ? r : al * r;
        r = p0.y + b0.y; o4.y = r > 0.f ? r : al * r;
        r = p1.x + b0.z; o4.z = r > 0.f ? r : al * r;
        r = p1.y + b0.w; o4.w = r > 0.f ? r : al * r;
        reinterpret_cast<float4*>(op)[0] = o4;
        r = p2.x + b1.x; o4.x = r > 0.f ? r : al * r;
        r = p2.y + b1.y; o4.y = r > 0.f ? r : al * r;
        r = p3.x + b1.z; o4.z = r > 0.f ? r : al * r;
        r = p3.y + b1.w; o4.w = r > 0.f ? r : al * r;
        reinterpret_cast<float4*>(op)[1] = o4;
    }
}

// ---------------------------------------------------------------------------
// Forward-warp scatter: NHWC src, NHWC acc (den at channel C), v4 reductions.
// ---------------------------------------------------------------------------
template<int C4, int CA>
__global__ void scatter_kernel(const float* __restrict__ src,
                               const float* __restrict__ flow,
                               float* __restrict__ acc, int Hs, int Ws) {
    constexpr int C = 4 * C4;
    const int HWs = Hs * Ws;
    int id = blockIdx.x * blockDim.x + threadIdx.x;
    if (id >= BB * HWs) return;
    int b = id / HWs;
    int p = id - b * HWs;
    int y = p / Ws;
    int x = p - y * Ws;
    const float* fb = flow + (size_t)b * 2 * HWs;
    float fx = fb[p], fy = fb[HWs + p];
    float txf = x + fx, tyf = y + fy;
    float x0f = floorf(txf), y0f = floorf(tyf);
    float dx = txf - x0f, dy = tyf - y0f;
    int x0 = (int)x0f, y0 = (int)y0f;
    float w[4] = { (1.f - dx) * (1.f - dy), dx * (1.f - dy),
                   (1.f - dx) * dy,         dx * dy };
    int xs[4] = { x0, x0 + 1, x0, x0 + 1 };
    int ys[4] = { y0, y0, y0 + 1, y0 + 1 };
    int idxs[4];
    bool ok[4];
#pragma unroll
    for (int k = 0; k < 4; k++) {
        ok[k] = xs[k] >= 0 && xs[k] < Ws && ys[k] >= 0 && ys[k] < Hs && w[k] > 0.f;
        idxs[k] = ys[k] * Ws + xs[k];
    }
    float* accB = acc + (size_t)b * HWs * CA;
    const float4* sp = reinterpret_cast<const float4*>(src + (size_t)id * C);
#pragma unroll
    for (int c4 = 0; c4 < C4; c4++) {
        float4 v = sp[c4];
#pragma unroll
        for (int k = 0; k < 4; k++) {
            if (ok[k])
                red4(accB + (size_t)idxs[k] * CA + 4 * c4,
                     v.x * w[k], v.y * w[k], v.z * w[k], v.w * w[k]);
        }
    }
#pragma unroll
    for (int k = 0; k < 4; k++)
        if (ok[k]) atomicAdd(accB + (size_t)idxs[k] * CA + C, w[k]);
}

// ---------------------------------------------------------------------------
// Finalize: NHWC acc -> divide by den -> NCHW output sections
// ---------------------------------------------------------------------------
template<int C, int CA>
__global__ void finalize_simple(const float* __restrict__ acc,
                                float* __restrict__ outsec,
                                int Ctot, int coff, int HWs) {
    __shared__ float s[64 * (CA + 1)];
    __shared__ float inv[64];
    const int base = blockIdx.x * 64;
    const int tid = threadIdx.x;
    constexpr int Q = CA / 4;
    for (int idx = tid; idx < 64 * Q; idx += 256) {
        int p = idx / Q, q = idx - (idx / Q) * Q;
        float4 v = *reinterpret_cast<const float4*>(acc + ((size_t)(base + p)) * CA + 4 * q);
        s[p * (CA + 1) + 4 * q + 0] = v.x;
        s[p * (CA + 1) + 4 * q + 1] = v.y;
        s[p * (CA + 1) + 4 * q + 2] = v.z;
        s[p * (CA + 1) + 4 * q + 3] = v.w;
    }
    __syncthreads();
    if (tid < 64) inv[tid] = 1.f / fmaxf(s[tid * (CA + 1) + C], 1e-7f);
    __syncthreads();
    const int b = base / HWs;
    const int p0 = base - b * HWs;
    for (int id = tid; id < C * 64; id += 256) {
        int c = id >> 6, i = id & 63;
        outsec[((size_t)(b * Ctot + coff + c)) * HWs + p0 + i] = s[i * (CA + 1) + c] * inv[i];
    }
}

// full-res: channels 0-31 -> SEC1(feat), 32-34 -> SEC0(img), 35 -> SEC4(sig)
__global__ void finalize_full(const float* __restrict__ acc,
                              float* __restrict__ out, int sel) {
    __shared__ float s[64 * 41];
    __shared__ float inv[64];
    const int base = blockIdx.x * 64;
    const int tid = threadIdx.x;
    for (int idx = tid; idx < 64 * 10; idx += 256) {
        int p = idx / 10, q = idx - (idx / 10) * 10;
        float4 v = *reinterpret_cast<const float4*>(acc + ((size_t)(base + p)) * CFA + 4 * q);
        s[p * 41 + 4 * q + 0] = v.x;
        s[p * 41 + 4 * q + 1] = v.y;
        s[p * 41 + 4 * q + 2] = v.z;
        s[p * 41 + 4 * q + 3] = v.w;
    }
    __syncthreads();
    if (tid < 64) inv[tid] = 1.f / fmaxf(s[tid * 41 + 36], 1e-7f);
    __syncthreads();
    const int b = base / HWF;
    const int p0 = base - b * HWF;
    for (int id = tid; id < 36 * 64; id += 256) {
        int c = id >> 6, i = id & 63;
        float val = s[i * 41 + c] * inv[i];
        size_t dst;
        if (c < 32)       dst = SEC1 + ((size_t)(b * 64 + 32 * sel + c)) * HWF + p0 + i;
        else if (c < 35)  dst = SEC0 + ((size_t)(b * 6 + 3 * sel + (c - 32))) * HWF + p0 + i;
        else              dst = SEC4 + ((size_t)(b * 2 + sel)) * HWF + p0 + i;
        out[dst] = val;
    }
}

// ---------------------------------------------------------------------------
// Host launcher with multi-stream graph (forked from capturing default stream)
// ---------------------------------------------------------------------------
static inline int div_up(long long a, int b) { return (int)((a + b - 1) / b); }

extern "C" void kernel_launch(void* const* d_in, const int* in_sizes, int n_in,
                              void* d_out, int out_size) {
    const float* img0    = (const float*)d_in[0];
    const float* img1    = (const float*)d_in[1];
    const float* flow01  = (const float*)d_in[2];
    const float* sigma01 = (const float*)d_in[3];
    const float* flow10  = (const float*)d_in[4];
    const float* sigma10 = (const float*)d_in[5];
    const float *w[6], *bi[6], *al[6];
    for (int i = 0; i < 6; i++) {
        w[i]  = (const float*)d_in[6 + 3 * i];
        bi[i] = (const float*)d_in[7 + 3 * i];
        al[i] = (const float*)d_in[8 + 3 * i];
    }
    float* out = (float*)d_out;

    float *p_srcF, *p_accF, *p_srcH, *p_accH, *p_srcQ, *p_accQ;
    float *p_bufA, *p_bufB, *p_bufC, *p_f0t, *p_f1t, *p_fH, *p_fQ, *p_mean;
    cudaGetSymbolAddress((void**)&p_srcF, g_srcF);
    cudaGetSymbolAddress((void**)&p_accF, g_accF);
    cudaGetSymbolAddress((void**)&p_srcH, g_srcH);
    cudaGetSymbolAddress((void**)&p_accH, g_accH);
    cudaGetSymbolAddress((void**)&p_srcQ, g_srcQ);
    cudaGetSymbolAddress((void**)&p_accQ, g_accQ);
    cudaGetSymbolAddress((void**)&p_bufA, g_bufA);
    cudaGetSymbolAddress((void**)&p_bufB, g_bufB);
    cudaGetSymbolAddress((void**)&p_bufC, g_bufC);
    cudaGetSymbolAddress((void**)&p_f0t,  g_flow0t);
    cudaGetSymbolAddress((void**)&p_f1t,  g_flow1t);
    cudaGetSymbolAddress((void**)&p_fH,   g_flowH);
    cudaGetSymbolAddress((void**)&p_fQ,   g_flowQ);
    cudaGetSymbolAddress((void**)&p_mean, g_meanAcc);

    const size_t szSF = (size_t)BB * HWF * CF;
    const size_t szAF = (size_t)BB * HWF * CFA;
    const size_t szSH = (size_t)BB * HW2 * CHh;
    const size_t szAH = (size_t)BB * HW2 * CHA;
    const size_t szSQ = (size_t)BB * HW4 * CQ;
    const size_t szAQ = (size_t)BB * HW4 * CQA;

    // Lazily-created side streams + events (first call is the uncaptured
    // correctness run, so creation happens outside graph capture).
    static cudaStream_t sA = nullptr, sB = nullptr, sC = nullptr;
    static cudaEvent_t evRoot, evMean, evC2, evC4, evS1, evSB, evSC;
    if (!sA) {
        cudaStreamCreateWithFlags(&sA, cudaStreamNonBlocking);
        cudaStreamCreateWithFlags(&sB, cudaStreamNonBlocking);
        cudaStreamCreateWithFlags(&sC, cudaStreamNonBlocking);
        cudaEventCreateWithFlags(&evRoot, cudaEventDisableTiming);
        cudaEventCreateWithFlags(&evMean, cudaEventDisableTiming);
        cudaEventCreateWithFlags(&evC2,   cudaEventDisableTiming);
        cudaEventCreateWithFlags(&evC4,   cudaEventDisableTiming);
        cudaEventCreateWithFlags(&evS1,   cudaEventDisableTiming);
        cudaEventCreateWithFlags(&evSB,   cudaEventDisableTiming);
        cudaEventCreateWithFlags(&evSC,   cudaEventDisableTiming);
    }

    // ---- main stream M (default): mean chain + conv chain ----
    cudaEventRecord(evRoot, 0);

    zero_mean_kernel<<<1, 32>>>(p_mean);
    mean_partial_kernel<<<BB * 32, 256>>>(img0, img1, p_mean);
    cudaEventRecord(evMean, 0);

    conv1_kernel<16, 4, 4><<<dim3(7, 64, 8), dim3(16, 4)>>>(
        img0, img1, p_mean, w[0], bi[0], al[0], p_bufA);
    // launch index 3 (ncu-profiled): conv2, padded vectorized-input kernel
    conv_wide2<8, 1, 8, 4, 8, 4, 1><<<dim3(14, 32, 8), dim3(16, 8)>>>(
        p_bufA, 32, 32, w[1], bi[1], al[1], p_srcF, CF, 32, HH, WW, HH, WW);
    cudaEventRecord(evC2, 0);

    // conv3: stride2, unpadded 128-thr (R11-best shape)
    conv_wide2<8, 2, 8, 4, 8, 2, 0><<<dim3(7, 16, 16), dim3(16, 8)>>>(
        p_srcF, CF, 32, w[2], bi[2], al[2], p_bufB, 64, 64, HH, WW, H2, W2);
    conv_wide2<8, 1, 8, 4, 8, 4, 1><<<dim3(7, 16, 16), dim3(16, 8)>>>(
        p_bufB, 64, 64, w[3], bi[3], al[3], p_srcH, CHh, 64, H2, W2, H2, W2);
    cudaEventRecord(evC4, 0);

    conv_wide2<8, 2, 8, 2, 8, 2, 0><<<dim3(7, 8, 24), dim3(8, 8)>>>(
        p_srcH, CHh, 64, w[4], bi[4], al[4], p_bufC, 96, 96, H2, W2, H4, W4);
    conv_wide2<8, 1, 8, 2, 8, 2, 1><<<dim3(7, 8, 24), dim3(8, 8)>>>(
        p_bufC, 96, 96, w[5], bi[5], al[5], p_srcQ, CQ, 96, H4, W4, H4, W4);

    // ---- stream A: flows + acc zeros + prep (overlaps conv chain) ----
    cudaStreamWaitEvent(sA, evRoot, 0);
    interflow_kernel<<<div_up(2LL * BB * HWF, 256), 256, 0, sA>>>(
        flow01, sigma01, flow10, sigma10, p_f0t, p_f1t);
    downflow_kernel<<<div_up((long long)BB * 2 * HW2, 256), 256, 0, sA>>>(p_f0t, p_fH, 2, H2, W2);
    downflow_kernel<<<div_up((long long)BB * 2 * HW2, 256), 256, 0, sA>>>(p_f1t, p_fH + (size_t)BB * 2 * HW2, 2, H2, W2);
    downflow_kernel<<<div_up((long long)BB * 2 * HW4, 256), 256, 0, sA>>>(p_f0t, p_fQ, 4, H4, W4);
    downflow_kernel<<<div_up((long long)BB * 2 * HW4, 256), 256, 0, sA>>>(p_f1t, p_fQ + (size_t)BB * 2 * HW4, 4, H4, W4);
    zero_kernel<<<div_up(2LL * szAF / 4, 256), 256, 0, sA>>>((float4*)p_accF, 2LL * szAF / 4);
    zero_kernel<<<div_up(2LL * szAH / 4, 256), 256, 0, sA>>>((float4*)p_accH, 2LL * szAH / 4);
    zero_kernel<<<div_up(2LL * szAQ / 4, 256), 256, 0, sA>>>((float4*)p_accQ, 2LL * szAQ / 4);
    cudaStreamWaitEvent(sA, evMean, 0);
    prep_kernel<<<div_up(2LL * BB * HWF, 256), 256, 0, sA>>>(
        img0, img1, sigma01, sigma10, p_mean, p_srcF, p_srcF + szSF);
    cudaEventRecord(evS1, sA);

    // ---- stream B: full-res scatter + finalize (overlaps conv3..6) ----
    cudaStreamWaitEvent(sB, evC2, 0);
    cudaStreamWaitEvent(sB, evS1, 0);
    for (int sel = 0; sel < 2; sel++) {
        const float* flF = sel ? p_f1t : p_f0t;
        scatter_kernel<9, CFA><<<div_up((long long)BB * HWF, 256), 256, 0, sB>>>(
            p_srcF + (size_t)sel * szSF, flF, p_accF + (size_t)sel * szAF, HH, WW);
    }
    for (int sel = 0; sel < 2; sel++)
        finalize_full<<<BB * HWF / 64, 256, 0, sB>>>(p_accF + (size_t)sel * szAF, out, sel);
    cudaEventRecord(evSB, sB);

    // ---- stream C: half-res scatter + finalize (overlaps conv5/6) ----
    cudaStreamWaitEvent(sC, evC4, 0);
    cudaStreamWaitEvent(sC, evS1, 0);
    for (int sel = 0; sel < 2; sel++) {
        const float* flH = p_fH + (size_t)sel * BB * 2 * HW2;
        scatter_kernel<16, CHA><<<div_up((long long)BB * HW2, 256), 256, 0, sC>>>(
            p_srcH + (size_t)sel * szSH, flH, p_accH + (size_t)sel * szAH, H2, W2);
    }
    for (int sel = 0; sel < 2; sel++)
        finalize_simple<CHh, CHA><<<BB * HW2 / 64, 256, 0, sC>>>(
            p_accH + (size_t)sel * szAH, out + SEC2, 128, 64 * sel, HW2);
    cudaEventRecord(evSC, sC);

    // ---- main stream tail: quarter-res after conv6 ----
    cudaStreamWaitEvent(0, evS1, 0);
    for (int sel = 0; sel < 2; sel++) {
        const float* flQ = p_fQ + (size_t)sel * BB * 2 * HW4;
        scatter_kernel<24, CQA><<<div_up((long long)BB * HW4, 256), 256>>>(
            p_srcQ + (size_t)sel * szSQ, flQ, p_accQ + (size_t)sel * szAQ, H4, W4);
    }
    for (int sel = 0; sel < 2; sel++)
        finalize_simple<CQ, CQA><<<BB * HW4 / 64, 256>>>(
            p_accQ + (size_t)sel * szAQ, out + SEC3, 192, 96 * sel, HW4);

    // ---- join side streams back into the default stream ----
    cudaStreamWaitEvent(0, evSB, 0);
    cudaStreamWaitEvent(0, evSC, 0);
}